// round 12
// baseline (speedup 1.0000x reference)
#include <cuda_runtime.h>

// Problem constants (match reference_code)
#define NN     512
#define NE     5
#define NL     12
#define MB     8192                 // 16 channels * 512 rows
#define NVOXP  (1u << 22)           // 16*512*512 elements per xp "element" slab
#define SCALE  1.953125e-5f         // SAMPLE_SIZE_CM / N = 0.01/512
#define KFAC   170.0f               // PROBE_CTS * FL_RATIO * SA_ADJ * SA_THETA

// out layout: fl_sig[NL][MB] followed by transmission[MB]

__global__ __launch_bounds__(512) void ppm_tex_kernel(
    cudaTextureObject_t t0, cudaTextureObject_t t1, cudaTextureObject_t t2,
    cudaTextureObject_t t3, cudaTextureObject_t t4,
    const float* __restrict__ attCS,     // (5,)
    const float* __restrict__ dfu,       // (12,)
    const float* __restrict__ theta_p,   // (1,)
    const int*   __restrict__ lidx,      // (12,)
    float* __restrict__ out)
{
    const int b    = blockIdx.x;       // 0..8191 == c*512 + h
    const int c    = b >> 9;
    const int h    = b & (NN - 1);
    const int w    = threadIdx.x;
    const int lane = w & 31;
    const int wid  = w >> 5;           // 16 warps

    // --- rotation coordinates (reference math) ---
    float sn, cs;
    sincosf(theta_p[0], &sn, &cs);
    const float inv = 1.0f / (float)NN;
    const float gx = (2.0f * (float)w + 1.0f) * inv - 1.0f;
    const float gy = (2.0f * (float)h + 1.0f) * inv - 1.0f;
    const float x_in = cs * gx - sn * gy;
    const float y_in = sn * gx + cs * gy;
    float ix = ((x_in + 1.0f) * (float)NN - 1.0f) * 0.5f;
    float iy = ((y_in + 1.0f) * (float)NN - 1.0f) * 0.5f;
    ix = fminf(fmaxf(ix, 0.0f), (float)(NN - 1));
    iy = fminf(fmaxf(iy, 0.0f), (float)(NN - 1));

    // HW bilinear: tex2D(linear) at (u+0.5, v+0.5) lerps texels floor(u),floor(u)+1.
    // iy clamped to <=511 => the second row has weight exactly 0 at iy==511, so the
    // stacked-channel texture (height 8192) never mixes channels with nonzero weight.
    const float xu = ix + 0.5f;
    const float yu = (float)(c << 9) + iy + 0.5f;

    float conc[NE];
    conc[0] = tex2D<float>(t0, xu, yu);
    conc[1] = tex2D<float>(t1, xu, yu);
    conc[2] = tex2D<float>(t2, xu, yu);
    conc[3] = tex2D<float>(t3, xu, yu);
    conc[4] = tex2D<float>(t4, xu, yu);

    float lac = 0.0f;
#pragma unroll
    for (int e = 0; e < NE; e++)
        lac = fmaf(__ldg(attCS + e), conc[e], lac);

    // --- block-wide inclusive scan of lac over 512 threads ---
    float v = lac;
#pragma unroll
    for (int o = 1; o < 32; o <<= 1) {
        const float n = __shfl_up_sync(0xffffffffu, v, o);
        if (lane >= o) v += n;
    }
    __shared__ float wsum[16];
    __shared__ float woff[16];
    if (lane == 31) wsum[wid] = v;
    __syncthreads();
    if (wid == 0) {
        float x = (lane < 16) ? wsum[lane] : 0.0f;
#pragma unroll
        for (int o = 1; o < 16; o <<= 1) {
            const float n = __shfl_up_sync(0xffffffffu, x, o);
            if (lane >= o) x += n;
        }
        if (lane < 16) woff[lane] = x;
    }
    __syncthreads();

    const float incl = v + (wid ? woff[wid - 1] : 0.0f);
    const float excl = incl - lac;
    const float atten = __expf(-excl * SCALE);

    // --- 5 block reductions of atten*conc[e] ---
    __shared__ float red[NE][16];
#pragma unroll
    for (int e = 0; e < NE; e++) {
        float s = atten * conc[e];
#pragma unroll
        for (int o = 16; o > 0; o >>= 1)
            s += __shfl_xor_sync(0xffffffffu, s, o);
        if (lane == 0) red[e][wid] = s;
    }
    __syncthreads();

    __shared__ float Ssh[NE];
    if (w < NE) {
        float s = 0.0f;
#pragma unroll
        for (int k = 0; k < 16; k++) s += red[w][k];
        Ssh[w] = s;
    }
    __syncthreads();

    // --- outputs ---
    if (w < NL) {
        out[w * MB + b] = KFAC * __ldg(dfu + w) * Ssh[__ldg(lidx + w)];
    }
    if (w == 0) {
        out[NL * MB + b] = woff[15] * SCALE;  // transmission
    }
}

extern "C" void kernel_launch(void* const* d_in, const int* in_sizes, int n_in,
                              void* d_out, int out_size)
{
    const float* xp      = (const float*)d_in[0];
    const float* attCS   = (const float*)d_in[1];
    const float* dfu     = (const float*)d_in[2];
    const float* theta_p = (const float*)d_in[3];
    const int*   lidx    = (const int*)d_in[4];
    float* out = (float*)d_out;

    // One texture per element slab: 512 x 8192 (16 channels stacked in y),
    // pitch 2048 B, fp32, bilinear filter, clamp addressing. Created once on
    // the first (uncaptured) correctness call; no device memory is allocated.
    static cudaTextureObject_t texs[NE] = {0, 0, 0, 0, 0};
    if (texs[0] == 0) {
        for (int e = 0; e < NE; e++) {
            cudaResourceDesc rd;
            memset(&rd, 0, sizeof(rd));
            rd.resType = cudaResourceTypePitch2D;
            rd.res.pitch2D.devPtr = (void*)(xp + (size_t)e * NVOXP);
            rd.res.pitch2D.desc = cudaCreateChannelDesc<float>();
            rd.res.pitch2D.width = NN;
            rd.res.pitch2D.height = 16 * NN;
            rd.res.pitch2D.pitchInBytes = NN * sizeof(float);

            cudaTextureDesc td;
            memset(&td, 0, sizeof(td));
            td.addressMode[0] = cudaAddressModeClamp;
            td.addressMode[1] = cudaAddressModeClamp;
            td.filterMode = cudaFilterModeLinear;
            td.readMode = cudaReadModeElementType;
            td.normalizedCoords = 0;

            cudaCreateTextureObject(&texs[e], &rd, &td, nullptr);
        }
    }

    ppm_tex_kernel<<<MB, 512>>>(texs[0], texs[1], texs[2], texs[3], texs[4],
                                attCS, dfu, theta_p, lidx, out);
}

// round 13
// speedup vs baseline: 1.5558x; 1.5558x over previous
#include <cuda_runtime.h>

// Problem constants
#define NN     512
#define NE     5
#define NL     12
#define MB     8192                 // 16 channels * 512 rows
#define NVOXP  (1u << 22)           // elements per xp slab
#define SCALE  1.953125e-5f         // SAMPLE_SIZE_CM / N = 0.01/512
#define KFAC   170.0f               // PROBE_CTS * FL_RATIO * SA_ADJ * SA_THETA
#define NCHUNK 8                    // 512 / 64 chunks per row

// scratch: per (row b, chunk): [T, S0..S4]
__device__ float g_scratch[MB * NCHUNK * 6];

// ─────────────── Pass A: tex-sampled rotate + chunk partials (64x64 tiles) ──
__global__ __launch_bounds__(512) void ppm_passA(
    cudaTextureObject_t t0, cudaTextureObject_t t1, cudaTextureObject_t t2,
    cudaTextureObject_t t3, cudaTextureObject_t t4,
    const float* __restrict__ attCS,     // (5,)
    const float* __restrict__ theta_p)   // (1,)
{
    const int tid  = threadIdx.x;
    const int lane = tid & 31;
    const int warp = tid >> 5;          // 0..15

    const int bid = blockIdx.x;         // 16c * 8tx * 8ty = 1024
    const int c   = bid >> 6;
    const int tx  = (bid >> 3) & 7;
    const int ty  = bid & 7;
    const int w0  = tx << 6;            // tile origin
    const int h0  = ty << 6;

    float sn, cs;
    sincosf(theta_p[0], &sn, &cs);
    const float inv = 1.0f / (float)NN;

    const float a0 = __ldg(attCS + 0), a1 = __ldg(attCS + 1), a2 = __ldg(attCS + 2),
                a3 = __ldg(attCS + 3), a4 = __ldg(attCS + 4);

    const float ybase = (float)(c << 9) + 0.5f;   // channel offset in stacked texture
    const float KA = 0.5f - 256.0f;

    // ---- 4 sweeps: warp handles tile rows warp+16k; lane = 2 adjacent w ----
#pragma unroll
    for (int sweep = 0; sweep < 4; sweep++) {
        const int r = warp + (sweep << 4);        // 0..63
        const int h = h0 + r;
        const int b = (c << 9) + h;
        const float gy = (2.0f * (float)h + 1.0f) * inv - 1.0f;
        const float BX = cs * KA - 256.0f * sn * gy + 255.5f;
        const float BY = sn * KA + 256.0f * cs * gy + 255.5f;

        const float wfl = (float)(w0 + (lane << 1));

        float conc[2][NE];
        float lacv[2];
#pragma unroll
        for (int j = 0; j < 2; j++) {
            float ix = fmaf(cs, wfl, BX) + (j ? cs : 0.0f);
            float iy = fmaf(sn, wfl, BY) + (j ? sn : 0.0f);
            ix = fminf(fmaxf(ix, 0.0f), (float)(NN - 1));
            iy = fminf(fmaxf(iy, 0.0f), (float)(NN - 1));
            // HW bilinear at (u+0.5, v+0.5); iy<=511 => row 512 has weight 0,
            // so the stacked-channel texture never mixes channels.
            const float xu = ix + 0.5f;
            const float yu = ybase + iy;

            conc[j][0] = tex2D<float>(t0, xu, yu);
            conc[j][1] = tex2D<float>(t1, xu, yu);
            conc[j][2] = tex2D<float>(t2, xu, yu);
            conc[j][3] = tex2D<float>(t3, xu, yu);
            conc[j][4] = tex2D<float>(t4, xu, yu);
            lacv[j] = a0 * conc[j][0] + a1 * conc[j][1] + a2 * conc[j][2]
                    + a3 * conc[j][3] + a4 * conc[j][4];
        }

        // warp inclusive scan of lane pair-sums -> local exclusive prefix within chunk
        const float pairsum = lacv[0] + lacv[1];
        float psc = pairsum;
#pragma unroll
        for (int o = 1; o < 32; o <<= 1) {
            const float n = __shfl_up_sync(0xffffffffu, psc, o);
            if (lane >= o) psc += n;
        }
        const float excl0 = psc - pairsum;
        const float at0 = __expf(-excl0 * SCALE);
        const float at1 = __expf(-(excl0 + lacv[0]) * SCALE);

        // locally attenuated per-element sums over the 64-wide chunk
        float S[NE];
#pragma unroll
        for (int e = 0; e < NE; e++) {
            float s = at0 * conc[0][e] + at1 * conc[1][e];
#pragma unroll
            for (int o = 16; o > 0; o >>= 1)
                s += __shfl_xor_sync(0xffffffffu, s, o);
            S[e] = s;
        }
        const float T = __shfl_sync(0xffffffffu, psc, 31);  // chunk lac total

        if (lane < 6) {
            float v = T;
            if (lane == 1) v = S[0];
            else if (lane == 2) v = S[1];
            else if (lane == 3) v = S[2];
            else if (lane == 4) v = S[3];
            else if (lane == 5) v = S[4];
            g_scratch[((size_t)(b << 3) + tx) * 6 + lane] = v;
        }
    }
}

// ───────────────── Pass B: cross-chunk combine + outputs (4 rows/warp) ──────
__global__ __launch_bounds__(256) void ppm_passB(
    const float* __restrict__ dfu,       // (12,)
    const int*   __restrict__ lidx,      // (12,)
    float* __restrict__ out)
{
    const int tid  = threadIdx.x;
    const int lane = tid & 31;
    const int warp = tid >> 5;
    const int g    = lane & 7;                     // chunk index
    const int rsub = lane >> 3;                    // row within warp (0..3)
    const int b    = ((blockIdx.x << 3) + warp) * 4 + rsub;

    const float* p = g_scratch + ((size_t)(b << 3) + g) * 6;
    float T  = p[0];
    float S0 = p[1], S1 = p[2], S2 = p[3], S3 = p[4], S4 = p[5];

    float incl = T;
#pragma unroll
    for (int o = 1; o < 8; o <<= 1) {
        const float n = __shfl_up_sync(0xffffffffu, incl, o, 8);
        if (g >= o) incl += n;
    }
    const float wfac = __expf(-(incl - T) * SCALE);   // exp(-chunk prefix)
    float t0 = wfac * S0, t1 = wfac * S1, t2 = wfac * S2, t3 = wfac * S3, t4 = wfac * S4;
#pragma unroll
    for (int o = 4; o > 0; o >>= 1) {
        t0 += __shfl_xor_sync(0xffffffffu, t0, o, 8);
        t1 += __shfl_xor_sync(0xffffffffu, t1, o, 8);
        t2 += __shfl_xor_sync(0xffffffffu, t2, o, 8);
        t3 += __shfl_xor_sync(0xffffffffu, t3, o, 8);
        t4 += __shfl_xor_sync(0xffffffffu, t4, o, 8);
    }
    const float Ttot = __shfl_sync(0xffffffffu, incl, 7, 8);

#pragma unroll
    for (int rep = 0; rep < 2; rep++) {
        const int idx = g + (rep << 3);
        if (idx < NL) {
            const int e = __ldg(lidx + idx);
            float se = t0;
            if (e == 1) se = t1; else if (e == 2) se = t2;
            else if (e == 3) se = t3; else if (e == 4) se = t4;
            out[idx * MB + b] = KFAC * __ldg(dfu + idx) * se;
        } else if (idx == NL) {
            out[NL * MB + b] = Ttot * SCALE;   // transmission
        }
    }
}

extern "C" void kernel_launch(void* const* d_in, const int* in_sizes, int n_in,
                              void* d_out, int out_size)
{
    const float* xp      = (const float*)d_in[0];
    const float* attCS   = (const float*)d_in[1];
    const float* dfu     = (const float*)d_in[2];
    const float* theta_p = (const float*)d_in[3];
    const int*   lidx    = (const int*)d_in[4];
    float* out = (float*)d_out;

    // One texture per element slab: 512 x 8192 (16 channels stacked in y),
    // fp32, bilinear, clamp. Created once on the first (uncaptured) call;
    // no device memory is allocated.
    static cudaTextureObject_t texs[NE] = {0, 0, 0, 0, 0};
    if (texs[0] == 0) {
        for (int e = 0; e < NE; e++) {
            cudaResourceDesc rd;
            memset(&rd, 0, sizeof(rd));
            rd.resType = cudaResourceTypePitch2D;
            rd.res.pitch2D.devPtr = (void*)(xp + (size_t)e * NVOXP);
            rd.res.pitch2D.desc = cudaCreateChannelDesc<float>();
            rd.res.pitch2D.width = NN;
            rd.res.pitch2D.height = 16 * NN;
            rd.res.pitch2D.pitchInBytes = NN * sizeof(float);

            cudaTextureDesc td;
            memset(&td, 0, sizeof(td));
            td.addressMode[0] = cudaAddressModeClamp;
            td.addressMode[1] = cudaAddressModeClamp;
            td.filterMode = cudaFilterModeLinear;
            td.readMode = cudaReadModeElementType;
            td.normalizedCoords = 0;

            cudaCreateTextureObject(&texs[e], &rd, &td, nullptr);
        }
    }

    ppm_passA<<<1024, 512>>>(texs[0], texs[1], texs[2], texs[3], texs[4],
                             attCS, theta_p);
    ppm_passB<<<MB / 32, 256>>>(dfu, lidx, out);
}

// round 14
// speedup vs baseline: 1.7587x; 1.1304x over previous
#include <cuda_runtime.h>

// Problem constants
#define NN     512
#define NE     5
#define NL     12
#define MB     8192                 // 16 channels * 512 rows
#define NVOXP  (1u << 22)           // elements per xp slab
#define SCALE  1.953125e-5f         // SAMPLE_SIZE_CM / N = 0.01/512
#define KFAC   170.0f               // PROBE_CTS * FL_RATIO * SA_ADJ * SA_THETA

// out layout: fl_sig[NL][MB] followed by transmission[MB]

// ───────── single kernel: warp = one output row, 8 sequential 64-px chunks ──
__global__ __launch_bounds__(256) void ppm_row_kernel(
    cudaTextureObject_t t0, cudaTextureObject_t t1, cudaTextureObject_t t2,
    cudaTextureObject_t t3, cudaTextureObject_t t4,
    const float* __restrict__ attCS,     // (5,)
    const float* __restrict__ dfu,       // (12,)
    const float* __restrict__ theta_p,   // (1,)
    const int*   __restrict__ lidx,      // (12,)
    float* __restrict__ out)
{
    const int tid  = threadIdx.x;
    const int lane = tid & 31;
    const int warp = tid >> 5;                    // 0..7

    const int b = (blockIdx.x << 3) + warp;       // output row (8 rows/block; 8|512)
    const int c = b >> 9;
    const int h = b & (NN - 1);

    float sn, cs;
    sincosf(theta_p[0], &sn, &cs);
    const float inv = 1.0f / (float)NN;

    const float a0 = __ldg(attCS + 0), a1 = __ldg(attCS + 1), a2 = __ldg(attCS + 2),
                a3 = __ldg(attCS + 3), a4 = __ldg(attCS + 4);

    // affine: ix = cs*w + BX, iy = sn*w + BY  (reference math, reassociated)
    const float KA = 0.5f - 256.0f;
    const float gy = (2.0f * (float)h + 1.0f) * inv - 1.0f;
    const float BX = cs * KA - 256.0f * sn * gy + 255.5f;
    const float BY = sn * KA + 256.0f * cs * gy + 255.5f;
    const float ybase = (float)(c << 9) + 0.5f;   // channel offset in stacked texture

    float carry = 0.0f;                            // running lac prefix (row scan)
    float acc[NE] = {0.0f, 0.0f, 0.0f, 0.0f, 0.0f};

#pragma unroll
    for (int ch = 0; ch < 8; ch++) {
        const float wfl = (float)((ch << 6) + (lane << 1));

        float conc[2][NE];
        float lacv[2];
#pragma unroll
        for (int j = 0; j < 2; j++) {
            float ix = fmaf(cs, wfl, BX) + (j ? cs : 0.0f);
            float iy = fmaf(sn, wfl, BY) + (j ? sn : 0.0f);
            ix = fminf(fmaxf(ix, 0.0f), (float)(NN - 1));
            iy = fminf(fmaxf(iy, 0.0f), (float)(NN - 1));
            // HW bilinear at (u+0.5, v+0.5); iy<=511 => row 512 weight exactly 0,
            // so the stacked-channel texture never mixes channels.
            const float xu = ix + 0.5f;
            const float yu = ybase + iy;

            conc[j][0] = tex2D<float>(t0, xu, yu);
            conc[j][1] = tex2D<float>(t1, xu, yu);
            conc[j][2] = tex2D<float>(t2, xu, yu);
            conc[j][3] = tex2D<float>(t3, xu, yu);
            conc[j][4] = tex2D<float>(t4, xu, yu);
            lacv[j] = a0 * conc[j][0] + a1 * conc[j][1] + a2 * conc[j][2]
                    + a3 * conc[j][3] + a4 * conc[j][4];
        }

        // warp inclusive scan of lane pair-sums within the 64-px chunk
        const float pairsum = lacv[0] + lacv[1];
        float psc = pairsum;
#pragma unroll
        for (int o = 1; o < 32; o <<= 1) {
            const float n = __shfl_up_sync(0xffffffffu, psc, o);
            if (lane >= o) psc += n;
        }
        const float excl0 = carry + (psc - pairsum);   // row-wide exclusive prefix
        const float at0 = __expf(-excl0 * SCALE);
        const float at1 = __expf(-(excl0 + lacv[0]) * SCALE);

#pragma unroll
        for (int e = 0; e < NE; e++)
            acc[e] = fmaf(at0, conc[0][e], fmaf(at1, conc[1][e], acc[e]));

        carry += __shfl_sync(0xffffffffu, psc, 31);    // add chunk total
    }

    // one warp-wide reduction per element at row end (all lanes get totals)
#pragma unroll
    for (int e = 0; e < NE; e++) {
#pragma unroll
        for (int o = 16; o > 0; o >>= 1)
            acc[e] += __shfl_xor_sync(0xffffffffu, acc[e], o);
    }

    // outputs: lanes 0..7 write up to 2 values each (12 fl_sig + transmission)
#pragma unroll
    for (int rep = 0; rep < 2; rep++) {
        const int idx = lane + (rep << 3);
        if (lane < 8) {
            if (idx < NL) {
                const int e = __ldg(lidx + idx);
                float se = acc[0];
                if (e == 1) se = acc[1]; else if (e == 2) se = acc[2];
                else if (e == 3) se = acc[3]; else if (e == 4) se = acc[4];
                out[idx * MB + b] = KFAC * __ldg(dfu + idx) * se;
            } else if (idx == NL) {
                out[NL * MB + b] = carry * SCALE;       // transmission
            }
        }
    }
}

extern "C" void kernel_launch(void* const* d_in, const int* in_sizes, int n_in,
                              void* d_out, int out_size)
{
    const float* xp      = (const float*)d_in[0];
    const float* attCS   = (const float*)d_in[1];
    const float* dfu     = (const float*)d_in[2];
    const float* theta_p = (const float*)d_in[3];
    const int*   lidx    = (const int*)d_in[4];
    float* out = (float*)d_out;

    // One texture per element slab: 512 x 8192 (16 channels stacked in y),
    // fp32, bilinear, clamp. Created once on the first (uncaptured) call;
    // no device memory is allocated.
    static cudaTextureObject_t texs[NE] = {0, 0, 0, 0, 0};
    if (texs[0] == 0) {
        for (int e = 0; e < NE; e++) {
            cudaResourceDesc rd;
            memset(&rd, 0, sizeof(rd));
            rd.resType = cudaResourceTypePitch2D;
            rd.res.pitch2D.devPtr = (void*)(xp + (size_t)e * NVOXP);
            rd.res.pitch2D.desc = cudaCreateChannelDesc<float>();
            rd.res.pitch2D.width = NN;
            rd.res.pitch2D.height = 16 * NN;
            rd.res.pitch2D.pitchInBytes = NN * sizeof(float);

            cudaTextureDesc td;
            memset(&td, 0, sizeof(td));
            td.addressMode[0] = cudaAddressModeClamp;
            td.addressMode[1] = cudaAddressModeClamp;
            td.filterMode = cudaFilterModeLinear;
            td.readMode = cudaReadModeElementType;
            td.normalizedCoords = 0;

            cudaCreateTextureObject(&texs[e], &rd, &td, nullptr);
        }
    }

    ppm_row_kernel<<<MB / 8, 256>>>(texs[0], texs[1], texs[2], texs[3], texs[4],
                                    attCS, dfu, theta_p, lidx, out);
}

// round 15
// speedup vs baseline: 1.7606x; 1.0011x over previous
#include <cuda_runtime.h>

// Problem constants
#define NN     512
#define NE     5
#define NL     12
#define MB     8192                 // 16 channels * 512 rows
#define NVOXP  (1u << 22)           // elements per xp slab
#define SCALE  1.953125e-5f         // SAMPLE_SIZE_CM / N = 0.01/512
#define KFAC   170.0f               // PROBE_CTS * FL_RATIO * SA_ADJ * SA_THETA

// out layout: fl_sig[NL][MB] followed by transmission[MB]

// ── single kernel: warp = TWO adjacent output rows, 8 sequential 64-px chunks ──
__global__ __launch_bounds__(128) void ppm_row2_kernel(
    cudaTextureObject_t t0, cudaTextureObject_t t1, cudaTextureObject_t t2,
    cudaTextureObject_t t3, cudaTextureObject_t t4,
    const float* __restrict__ attCS,     // (5,)
    const float* __restrict__ dfu,       // (12,)
    const float* __restrict__ theta_p,   // (1,)
    const int*   __restrict__ lidx,      // (12,)
    float* __restrict__ out)
{
    const int tid  = threadIdx.x;
    const int lane = tid & 31;
    const int warp = tid >> 5;                    // 0..3

    const int bA = ((blockIdx.x << 2) + warp) << 1;   // rows bA, bA+1 (same channel: 2|512)
    const int bB = bA + 1;
    const int c  = bA >> 9;
    const int hA = bA & (NN - 1);
    const int hB = hA + 1;

    float sn, cs;
    sincosf(theta_p[0], &sn, &cs);
    const float inv = 1.0f / (float)NN;

    const float a0 = __ldg(attCS + 0), a1 = __ldg(attCS + 1), a2 = __ldg(attCS + 2),
                a3 = __ldg(attCS + 3), a4 = __ldg(attCS + 4);

    // affine: ix = cs*w + BX(row), iy = sn*w + BY(row)
    const float KA = 0.5f - 256.0f;
    const float gyA = (2.0f * (float)hA + 1.0f) * inv - 1.0f;
    const float gyB = (2.0f * (float)hB + 1.0f) * inv - 1.0f;
    const float BXA = cs * KA - 256.0f * sn * gyA + 255.5f;
    const float BYA = sn * KA + 256.0f * cs * gyA + 255.5f;
    const float BXB = cs * KA - 256.0f * sn * gyB + 255.5f;
    const float BYB = sn * KA + 256.0f * cs * gyB + 255.5f;
    const float ybase = (float)(c << 9) + 0.5f;   // channel offset in stacked texture

    float carryA = 0.0f, carryB = 0.0f;
    float accA[NE] = {0.0f, 0.0f, 0.0f, 0.0f, 0.0f};
    float accB[NE] = {0.0f, 0.0f, 0.0f, 0.0f, 0.0f};

#pragma unroll
    for (int ch = 0; ch < 8; ch++) {
        const float wfl = (float)((ch << 6) + (lane << 1));

        float concA[2][NE], concB[2][NE];
        float lacA[2], lacB[2];
#pragma unroll
        for (int j = 0; j < 2; j++) {
            const float dj = j ? cs : 0.0f;
            const float ej = j ? sn : 0.0f;

            float ixA = fmaf(cs, wfl, BXA) + dj;
            float iyA = fmaf(sn, wfl, BYA) + ej;
            ixA = fminf(fmaxf(ixA, 0.0f), (float)(NN - 1));
            iyA = fminf(fmaxf(iyA, 0.0f), (float)(NN - 1));
            const float xuA = ixA + 0.5f;
            const float yuA = ybase + iyA;

            float ixB = fmaf(cs, wfl, BXB) + dj;
            float iyB = fmaf(sn, wfl, BYB) + ej;
            ixB = fminf(fmaxf(ixB, 0.0f), (float)(NN - 1));
            iyB = fminf(fmaxf(iyB, 0.0f), (float)(NN - 1));
            const float xuB = ixB + 0.5f;
            const float yuB = ybase + iyB;

            // HW bilinear at (u+0.5, v+0.5); iy<=511 keeps channels unmixed.
            concA[j][0] = tex2D<float>(t0, xuA, yuA);
            concB[j][0] = tex2D<float>(t0, xuB, yuB);
            concA[j][1] = tex2D<float>(t1, xuA, yuA);
            concB[j][1] = tex2D<float>(t1, xuB, yuB);
            concA[j][2] = tex2D<float>(t2, xuA, yuA);
            concB[j][2] = tex2D<float>(t2, xuB, yuB);
            concA[j][3] = tex2D<float>(t3, xuA, yuA);
            concB[j][3] = tex2D<float>(t3, xuB, yuB);
            concA[j][4] = tex2D<float>(t4, xuA, yuA);
            concB[j][4] = tex2D<float>(t4, xuB, yuB);

            lacA[j] = a0 * concA[j][0] + a1 * concA[j][1] + a2 * concA[j][2]
                    + a3 * concA[j][3] + a4 * concA[j][4];
            lacB[j] = a0 * concB[j][0] + a1 * concB[j][1] + a2 * concB[j][2]
                    + a3 * concB[j][3] + a4 * concB[j][4];
        }

        // two independent warp scans, interleaved in the issue slots
        const float psA = lacA[0] + lacA[1];
        const float psB = lacB[0] + lacB[1];
        float scA = psA, scB = psB;
#pragma unroll
        for (int o = 1; o < 32; o <<= 1) {
            const float nA = __shfl_up_sync(0xffffffffu, scA, o);
            const float nB = __shfl_up_sync(0xffffffffu, scB, o);
            if (lane >= o) { scA += nA; scB += nB; }
        }
        const float exA = carryA + (scA - psA);
        const float exB = carryB + (scB - psB);
        const float at0A = __expf(-exA * SCALE);
        const float at0B = __expf(-exB * SCALE);
        const float at1A = __expf(-(exA + lacA[0]) * SCALE);
        const float at1B = __expf(-(exB + lacB[0]) * SCALE);

#pragma unroll
        for (int e = 0; e < NE; e++) {
            accA[e] = fmaf(at0A, concA[0][e], fmaf(at1A, concA[1][e], accA[e]));
            accB[e] = fmaf(at0B, concB[0][e], fmaf(at1B, concB[1][e], accB[e]));
        }

        carryA += __shfl_sync(0xffffffffu, scA, 31);
        carryB += __shfl_sync(0xffffffffu, scB, 31);
    }

    // warp-wide reductions (dual, interleaved)
#pragma unroll
    for (int e = 0; e < NE; e++) {
#pragma unroll
        for (int o = 16; o > 0; o >>= 1) {
            accA[e] += __shfl_xor_sync(0xffffffffu, accA[e], o);
            accB[e] += __shfl_xor_sync(0xffffffffu, accB[e], o);
        }
    }

    // outputs: lanes 0..7 -> row A, lanes 16..23 -> row B (13 values each)
    const int half = lane >> 4;           // 0: row A, 1: row B
    const int l8   = lane & 15;
    if (l8 < 8) {
        const int   b   = half ? bB : bA;
        const float* ac = half ? accB : accA;
        const float cry = half ? carryB : carryA;
#pragma unroll
        for (int rep = 0; rep < 2; rep++) {
            const int idx = l8 + (rep << 3);
            if (idx < NL) {
                const int e = __ldg(lidx + idx);
                float se = ac[0];
                if (e == 1) se = ac[1]; else if (e == 2) se = ac[2];
                else if (e == 3) se = ac[3]; else if (e == 4) se = ac[4];
                out[idx * MB + b] = KFAC * __ldg(dfu + idx) * se;
            } else if (idx == NL) {
                out[NL * MB + b] = cry * SCALE;    // transmission
            }
        }
    }
}

extern "C" void kernel_launch(void* const* d_in, const int* in_sizes, int n_in,
                              void* d_out, int out_size)
{
    const float* xp      = (const float*)d_in[0];
    const float* attCS   = (const float*)d_in[1];
    const float* dfu     = (const float*)d_in[2];
    const float* theta_p = (const float*)d_in[3];
    const int*   lidx    = (const int*)d_in[4];
    float* out = (float*)d_out;

    // One texture per element slab: 512 x 8192 (16 channels stacked in y),
    // fp32, bilinear, clamp. Created once on the first (uncaptured) call;
    // no device memory is allocated.
    static cudaTextureObject_t texs[NE] = {0, 0, 0, 0, 0};
    if (texs[0] == 0) {
        for (int e = 0; e < NE; e++) {
            cudaResourceDesc rd;
            memset(&rd, 0, sizeof(rd));
            rd.resType = cudaResourceTypePitch2D;
            rd.res.pitch2D.devPtr = (void*)(xp + (size_t)e * NVOXP);
            rd.res.pitch2D.desc = cudaCreateChannelDesc<float>();
            rd.res.pitch2D.width = NN;
            rd.res.pitch2D.height = 16 * NN;
            rd.res.pitch2D.pitchInBytes = NN * sizeof(float);

            cudaTextureDesc td;
            memset(&td, 0, sizeof(td));
            td.addressMode[0] = cudaAddressModeClamp;
            td.addressMode[1] = cudaAddressModeClamp;
            td.filterMode = cudaFilterModeLinear;
            td.readMode = cudaReadModeElementType;
            td.normalizedCoords = 0;

            cudaCreateTextureObject(&texs[e], &rd, &td, nullptr);
        }
    }

    ppm_row2_kernel<<<MB / 8, 128>>>(texs[0], texs[1], texs[2], texs[3], texs[4],
                                     attCS, dfu, theta_p, lidx, out);
}

// round 16
// speedup vs baseline: 1.7761x; 1.0088x over previous
#include <cuda_runtime.h>

// Problem constants
#define NN     512
#define NE     5
#define NL     12
#define MB     8192                 // 16 channels * 512 rows
#define NVOXP  (1u << 22)           // elements per xp slab
#define SCALE  1.953125e-5f         // SAMPLE_SIZE_CM / N = 0.01/512
#define KFAC   170.0f               // PROBE_CTS * FL_RATIO * SA_ADJ * SA_THETA

// out layout: fl_sig[NL][MB] followed by transmission[MB]

// ── warp = one row, 8 chunks, SW-pipelined: fetch chunk k+1 before scan of k ──
__global__ __launch_bounds__(256, 4) void ppm_pipe_kernel(
    cudaTextureObject_t t0, cudaTextureObject_t t1, cudaTextureObject_t t2,
    cudaTextureObject_t t3, cudaTextureObject_t t4,
    const float* __restrict__ attCS,     // (5,)
    const float* __restrict__ dfu,       // (12,)
    const float* __restrict__ theta_p,   // (1,)
    const int*   __restrict__ lidx,      // (12,)
    float* __restrict__ out)
{
    const int tid  = threadIdx.x;
    const int lane = tid & 31;
    const int warp = tid >> 5;                    // 0..7

    const int b = (blockIdx.x << 3) + warp;       // output row
    const int c = b >> 9;
    const int h = b & (NN - 1);

    float sn, cs;
    sincosf(theta_p[0], &sn, &cs);
    const float inv = 1.0f / (float)NN;

    const float a0 = __ldg(attCS + 0), a1 = __ldg(attCS + 1), a2 = __ldg(attCS + 2),
                a3 = __ldg(attCS + 3), a4 = __ldg(attCS + 4);

    // affine: ix = cs*w + BX, iy = sn*w + BY (reference math, reassociated)
    const float KA = 0.5f - 256.0f;
    const float gy = (2.0f * (float)h + 1.0f) * inv - 1.0f;
    const float BX = cs * KA - 256.0f * sn * gy + 255.5f;
    const float BY = sn * KA + 256.0f * cs * gy + 255.5f;
    const float ybase = (float)(c << 9) + 0.5f;

    // fetch one 64-px chunk (2 px per lane) into dst[2][NE]
    auto fetch_chunk = [&](int ch, float dst[2][NE]) {
        const float wfl = (float)((ch << 6) + (lane << 1));
#pragma unroll
        for (int j = 0; j < 2; j++) {
            float ix = fmaf(cs, wfl, BX) + (j ? cs : 0.0f);
            float iy = fmaf(sn, wfl, BY) + (j ? sn : 0.0f);
            ix = fminf(fmaxf(ix, 0.0f), (float)(NN - 1));
            iy = fminf(fmaxf(iy, 0.0f), (float)(NN - 1));
            // HW bilinear at (u+0.5, v+0.5); iy<=511 => channel rows never mix.
            const float xu = ix + 0.5f;
            const float yu = ybase + iy;
            dst[j][0] = tex2D<float>(t0, xu, yu);
            dst[j][1] = tex2D<float>(t1, xu, yu);
            dst[j][2] = tex2D<float>(t2, xu, yu);
            dst[j][3] = tex2D<float>(t3, xu, yu);
            dst[j][4] = tex2D<float>(t4, xu, yu);
        }
    };

    float cur[2][NE], nxt[2][NE];
    fetch_chunk(0, cur);

    float carry = 0.0f;
    float acc[NE] = {0.0f, 0.0f, 0.0f, 0.0f, 0.0f};

#pragma unroll
    for (int ch = 0; ch < 8; ch++) {
        // issue next chunk's 10 tex fetches BEFORE the serial scan of this chunk
        if (ch < 7) fetch_chunk(ch + 1, nxt);

        const float lac0 = a0 * cur[0][0] + a1 * cur[0][1] + a2 * cur[0][2]
                         + a3 * cur[0][3] + a4 * cur[0][4];
        const float lac1 = a0 * cur[1][0] + a1 * cur[1][1] + a2 * cur[1][2]
                         + a3 * cur[1][3] + a4 * cur[1][4];

        // warp inclusive scan of lane pair-sums within the 64-px chunk
        const float pairsum = lac0 + lac1;
        float psc = pairsum;
#pragma unroll
        for (int o = 1; o < 32; o <<= 1) {
            const float n = __shfl_up_sync(0xffffffffu, psc, o);
            if (lane >= o) psc += n;
        }
        const float excl0 = carry + (psc - pairsum);   // row-wide exclusive prefix
        const float at0 = __expf(-excl0 * SCALE);
        const float at1 = __expf(-(excl0 + lac0) * SCALE);

#pragma unroll
        for (int e = 0; e < NE; e++)
            acc[e] = fmaf(at0, cur[0][e], fmaf(at1, cur[1][e], acc[e]));

        carry += __shfl_sync(0xffffffffu, psc, 31);    // add chunk total

        // rotate buffers (register renaming under full unroll)
        if (ch < 7) {
#pragma unroll
            for (int j = 0; j < 2; j++)
#pragma unroll
                for (int e = 0; e < NE; e++)
                    cur[j][e] = nxt[j][e];
        }
    }

    // one warp-wide reduction per element at row end
#pragma unroll
    for (int e = 0; e < NE; e++) {
#pragma unroll
        for (int o = 16; o > 0; o >>= 1)
            acc[e] += __shfl_xor_sync(0xffffffffu, acc[e], o);
    }

    // outputs: lanes 0..7 write up to 2 values each (12 fl_sig + transmission)
#pragma unroll
    for (int rep = 0; rep < 2; rep++) {
        const int idx = lane + (rep << 3);
        if (lane < 8) {
            if (idx < NL) {
                const int e = __ldg(lidx + idx);
                float se = acc[0];
                if (e == 1) se = acc[1]; else if (e == 2) se = acc[2];
                else if (e == 3) se = acc[3]; else if (e == 4) se = acc[4];
                out[idx * MB + b] = KFAC * __ldg(dfu + idx) * se;
            } else if (idx == NL) {
                out[NL * MB + b] = carry * SCALE;       // transmission
            }
        }
    }
}

extern "C" void kernel_launch(void* const* d_in, const int* in_sizes, int n_in,
                              void* d_out, int out_size)
{
    const float* xp      = (const float*)d_in[0];
    const float* attCS   = (const float*)d_in[1];
    const float* dfu     = (const float*)d_in[2];
    const float* theta_p = (const float*)d_in[3];
    const int*   lidx    = (const int*)d_in[4];
    float* out = (float*)d_out;

    // One texture per element slab: 512 x 8192 (16 channels stacked in y),
    // fp32, bilinear, clamp. Created once on the first (uncaptured) call;
    // no device memory is allocated.
    static cudaTextureObject_t texs[NE] = {0, 0, 0, 0, 0};
    if (texs[0] == 0) {
        for (int e = 0; e < NE; e++) {
            cudaResourceDesc rd;
            memset(&rd, 0, sizeof(rd));
            rd.resType = cudaResourceTypePitch2D;
            rd.res.pitch2D.devPtr = (void*)(xp + (size_t)e * NVOXP);
            rd.res.pitch2D.desc = cudaCreateChannelDesc<float>();
            rd.res.pitch2D.width = NN;
            rd.res.pitch2D.height = 16 * NN;
            rd.res.pitch2D.pitchInBytes = NN * sizeof(float);

            cudaTextureDesc td;
            memset(&td, 0, sizeof(td));
            td.addressMode[0] = cudaAddressModeClamp;
            td.addressMode[1] = cudaAddressModeClamp;
            td.filterMode = cudaFilterModeLinear;
            td.readMode = cudaReadModeElementType;
            td.normalizedCoords = 0;

            cudaCreateTextureObject(&texs[e], &rd, &td, nullptr);
        }
    }

    ppm_pipe_kernel<<<MB / 8, 256>>>(texs[0], texs[1], texs[2], texs[3], texs[4],
                                     attCS, dfu, theta_p, lidx, out);
}